// round 5
// baseline (speedup 1.0000x reference)
#include <cuda_runtime.h>
#include <cuda_bf16.h>
#include <cstdint>
#include <math.h>

#define NN 100000
#define NE 1600000
#define FD 128
#define NG 128
#define GF 32

// ---------------- scratch (device globals; no allocations allowed) ----------
__device__ __align__(16) __nv_bfloat16 g_Bh[2 * 128 * 256];   // W^T hi, per layer
__device__ __align__(16) __nv_bfloat16 g_Bl[2 * 128 * 256];   // W^T lo
__device__ __align__(16) float g_aggf[(size_t)NN * FD];       // fp32 neighbor mean
__device__ __align__(16) float g_h0[(size_t)NN * FD];
__device__ int   g_deg[NN];
__device__ int   g_rowptr[NN + 1];
__device__ int   g_fill[NN];
__device__ int   g_col[NE];
__device__ float g_psum[NG * FD];
__device__ float g_pmax[NG * FD];
__device__ int   g_pcnt[NG];
__device__ int   g_bsum[128];

// ---------------- small helpers ---------------------------------------------
__device__ __forceinline__ void atomicMaxF(float* addr, float v) {
    if (v >= 0.f) atomicMax((int*)addr, __float_as_int(v));
    else          atomicMin((unsigned int*)addr, __float_as_uint(v));
}

__device__ __forceinline__ void bsplit(float v, unsigned short& hi, unsigned short& lo) {
    __nv_bfloat16 h = __float2bfloat16(v);
    float r = v - __bfloat162float(h);
    __nv_bfloat16 l = __float2bfloat16(r);
    hi = __bfloat16_as_ushort(h);
    lo = __bfloat16_as_ushort(l);
}

__device__ __forceinline__ uint32_t smem_u32(const void* p) {
    uint32_t a;
    asm("{ .reg .u64 t; cvta.to.shared.u64 t, %1; cvt.u32.u64 %0, t; }"
        : "=r"(a) : "l"(p));
    return a;
}

__device__ __forceinline__ void ldsm4(uint32_t* r, uint32_t addr) {
    asm volatile("ldmatrix.sync.aligned.m8n8.x4.shared.b16 {%0,%1,%2,%3}, [%4];"
                 : "=r"(r[0]), "=r"(r[1]), "=r"(r[2]), "=r"(r[3]) : "r"(addr));
}
__device__ __forceinline__ void ldsm2(uint32_t* r, uint32_t addr) {
    asm volatile("ldmatrix.sync.aligned.m8n8.x2.shared.b16 {%0,%1}, [%2];"
                 : "=r"(r[0]), "=r"(r[1]) : "r"(addr));
}
__device__ __forceinline__ void mma_bf16(float* c, const uint32_t* a, const uint32_t* b) {
    asm volatile(
        "mma.sync.aligned.m16n8k16.row.col.f32.bf16.bf16.f32 "
        "{%0,%1,%2,%3}, {%4,%5,%6,%7}, {%8,%9}, {%0,%1,%2,%3};"
        : "+f"(c[0]), "+f"(c[1]), "+f"(c[2]), "+f"(c[3])
        : "r"(a[0]), "r"(a[1]), "r"(a[2]), "r"(a[3]), "r"(b[0]), "r"(b[1]));
}

// ---------------- CSR build -------------------------------------------------
__global__ void k_init() {
    int i = blockIdx.x * blockDim.x + threadIdx.x;
    if (i < NN) { g_deg[i] = 0; g_fill[i] = 0; }
    if (i < NG * FD) { g_psum[i] = 0.f; g_pmax[i] = -INFINITY; }
}

__global__ void k_hist(const int* __restrict__ edges) {
    int e = blockIdx.x * blockDim.x + threadIdx.x;
    if (e < NE) atomicAdd(&g_deg[edges[NE + e]], 1);
}

#define SCAN_B 1024
__global__ void k_scanA() {
    __shared__ int sm[SCAN_B];
    int i = blockIdx.x * SCAN_B + threadIdx.x;
    int v = (i < NN) ? g_deg[i] : 0;
    sm[threadIdx.x] = v;
    __syncthreads();
    for (int off = 1; off < SCAN_B; off <<= 1) {
        int t = (threadIdx.x >= off) ? sm[threadIdx.x - off] : 0;
        __syncthreads();
        sm[threadIdx.x] += t;
        __syncthreads();
    }
    if (i < NN) g_rowptr[i] = sm[threadIdx.x] - v;   // exclusive
    if (threadIdx.x == SCAN_B - 1) g_bsum[blockIdx.x] = sm[SCAN_B - 1];
}

__global__ void k_scanB(int nb) {                    // parallel Kogge-Stone
    __shared__ int s[128];
    int t = threadIdx.x;
    int v = (t < nb) ? g_bsum[t] : 0;
    s[t] = v;
    __syncthreads();
    for (int off = 1; off < 128; off <<= 1) {
        int u = (t >= off) ? s[t - off] : 0;
        __syncthreads();
        s[t] += u;
        __syncthreads();
    }
    if (t < nb) g_bsum[t] = s[t] - v;                // exclusive
}

__global__ void k_scanC() {
    int i = blockIdx.x * SCAN_B + threadIdx.x;
    if (i < NN) g_rowptr[i] += g_bsum[blockIdx.x];
    if (i == 0) g_rowptr[NN] = NE;
}

__global__ void k_fillcol(const int* __restrict__ edges) {
    int e = blockIdx.x * blockDim.x + threadIdx.x;
    if (e < NE) {
        int t = edges[NE + e];
        int p = g_rowptr[t] + atomicAdd(&g_fill[t], 1);
        g_col[p] = edges[e];
    }
}

// ---------------- per-graph node counts (sorted batch_idx) ------------------
__global__ void k_cnt(const int* __restrict__ batch) {
    int g = threadIdx.x;                             // 128 threads
    int lo = 0, hi = NN;
    while (lo < hi) { int mid = (lo + hi) >> 1; if (batch[mid] < g) lo = mid + 1; else hi = mid; }
    int lb = lo;
    lo = 0; hi = NN;
    while (lo < hi) { int mid = (lo + hi) >> 1; if (batch[mid] <= g) lo = mid + 1; else hi = mid; }
    g_pcnt[g] = lo - lb;
}

// ---------------- weight prep: V = [Wr;Wl] -> Bt[n][k] hi/lo bf16 -----------
__global__ void k_prepw(const float* __restrict__ Wr0, const float* __restrict__ Wl0,
                        const float* __restrict__ Wr1, const float* __restrict__ Wl1) {
    int idx = blockIdx.x * 256 + threadIdx.x;        // 65536 total
    int L = idx >> 15;
    int rem = idx & 32767;
    int k = rem >> 7, n = rem & 127;
    const float* Wr = L ? Wr1 : Wr0;
    const float* Wl = L ? Wl1 : Wl0;
    float v = (k < FD) ? Wr[k * FD + n] : Wl[(k - FD) * FD + n];
    unsigned short hi, lo;
    bsplit(v, hi, lo);
    g_Bh[L * 32768 + n * 256 + k] = __ushort_as_bfloat16(hi);
    g_Bl[L * 32768 + n * 256 + k] = __ushort_as_bfloat16(lo);
}

// ---------------- neighbor mean aggregation (fp32 out) ----------------------
__global__ void k_aggregate(const float* __restrict__ X) {
    int node = blockIdx.x * 8 + (threadIdx.x >> 5);
    int lane = threadIdx.x & 31;
    if (node >= NN) return;
    int beg = g_rowptr[node], end = g_rowptr[node + 1];
    const float4* Xv = (const float4*)X;
    float4 s = make_float4(0.f, 0.f, 0.f, 0.f);
    int e = beg;
    for (; e + 3 < end; e += 4) {
        int i0 = g_col[e], i1 = g_col[e + 1], i2 = g_col[e + 2], i3 = g_col[e + 3];
        float4 a = Xv[(size_t)i0 * 32 + lane];
        float4 b = Xv[(size_t)i1 * 32 + lane];
        float4 c = Xv[(size_t)i2 * 32 + lane];
        float4 d = Xv[(size_t)i3 * 32 + lane];
        s.x += (a.x + b.x) + (c.x + d.x);
        s.y += (a.y + b.y) + (c.y + d.y);
        s.z += (a.z + b.z) + (c.z + d.z);
        s.w += (a.w + b.w) + (c.w + d.w);
    }
    for (; e < end; e++) {
        float4 v = Xv[(size_t)g_col[e] * 32 + lane];
        s.x += v.x; s.y += v.y; s.z += v.z; s.w += v.w;
    }
    float sc = 1.f / fmaxf((float)(end - beg), 1.f);
    ((float4*)g_aggf)[(size_t)node * 32 + lane] =
        make_float4(s.x * sc, s.y * sc, s.z * sc, s.w * sc);
}

// ---------------- mma.sync GEMM: OUT = act([X|AGG] @ V + b), bf16x3 ---------
// CTA: 128 nodes x 128 outs; 8 warps 2(M)x4(N); warp tile 64x32; K=256 by 64.
// A loaded as fp32 and split to bf16 hi/lo on the fly. Optional fused pooling.
#define TP 72
#define TILE_B (128 * TP * 2)                 // 18432 bytes per tile
#define POOL_SEGS 16
#define GEMM_SMEM (4 * TILE_B + 512 + 512)

__device__ __forceinline__ void load_chunk_f32(__nv_bfloat16* dh, __nv_bfloat16* dl,
                                               const float* __restrict__ src,
                                               int row0, int kofs) {
    for (int i = threadIdx.x; i < 2048; i += 256) {  // float4 units: 128 x 16
        int r = i >> 4, q = (i & 15) * 4;
        int gr = row0 + r;
        float4 v = make_float4(0.f, 0.f, 0.f, 0.f);
        if (gr < NN) v = *(const float4*)(src + (size_t)gr * FD + kofs + q);
        union { unsigned short s[4]; uint2 u; } ph, pl;
        bsplit(v.x, ph.s[0], pl.s[0]);
        bsplit(v.y, ph.s[1], pl.s[1]);
        bsplit(v.z, ph.s[2], pl.s[2]);
        bsplit(v.w, ph.s[3], pl.s[3]);
        *(uint2*)(dh + r * TP + q) = ph.u;
        *(uint2*)(dl + r * TP + q) = pl.u;
    }
}

__device__ __forceinline__ void load_chunk_bf16(__nv_bfloat16* dst,
                                                const __nv_bfloat16* __restrict__ src,
                                                int kofs) {
    for (int i = threadIdx.x; i < 1024; i += 256) {  // uint4 units (8 bf16)
        int r = i >> 3, q = i & 7;
        uint4 v = *(const uint4*)(src + (size_t)r * 256 + kofs + q * 8);
        *(uint4*)(dst + r * TP + q * 8) = v;
    }
}

__global__ __launch_bounds__(256, 2) void k_gemm(
    const float* __restrict__ Xsrc, const float* __restrict__ AGGsrc,
    const __nv_bfloat16* __restrict__ Bh, const __nv_bfloat16* __restrict__ Bl,
    const float* __restrict__ bias, float* __restrict__ OUT,
    const int* __restrict__ batch, int relu, int pool)
{
    extern __shared__ char smem[];
    __nv_bfloat16* sAh = (__nv_bfloat16*)smem;
    __nv_bfloat16* sAl = (__nv_bfloat16*)(smem + TILE_B);
    __nv_bfloat16* sBh = (__nv_bfloat16*)(smem + 2 * TILE_B);
    __nv_bfloat16* sBl = (__nv_bfloat16*)(smem + 3 * TILE_B);
    float* sbias = (float*)(smem + 4 * TILE_B);
    int*   sbatch = (int*)(smem + 4 * TILE_B + 512);

    const int tid = threadIdx.x, wid = tid >> 5, lid = tid & 31;
    const int wm = wid >> 2, wn = wid & 3;
    const int node0 = blockIdx.x * 128;

    if (tid < FD) {
        sbias[tid] = bias[tid];
        if (pool) {
            int n = node0 + tid;
            sbatch[tid] = (n < NN) ? batch[n] : 0;
        }
    }

    float acc[4][4][4];
#pragma unroll
    for (int mt = 0; mt < 4; mt++)
#pragma unroll
        for (int nt = 0; nt < 4; nt++)
#pragma unroll
            for (int j = 0; j < 4; j++) acc[mt][nt][j] = 0.f;

    uint32_t aAh = smem_u32(sAh), aAl = smem_u32(sAl);
    uint32_t aBh = smem_u32(sBh), aBl = smem_u32(sBl);
    const uint32_t a_lane = (uint32_t)((lid & 15) * (TP * 2) + ((lid >> 4) << 4));
    const uint32_t b_lane = (uint32_t)((lid & 7) * (TP * 2) + (((lid >> 3) & 1) << 4));

    for (int c = 0; c < 4; c++) {
        const float* src = (c < 2) ? Xsrc : AGGsrc;
        load_chunk_f32(sAh, sAl, src, node0, (c & 1) * 64);
        load_chunk_bf16(sBh, Bh, c * 64);
        load_chunk_bf16(sBl, Bl, c * 64);
        __syncthreads();
#pragma unroll
        for (int ks = 0; ks < 4; ks++) {
            uint32_t ah[4][4], al[4][4];
#pragma unroll
            for (int mt = 0; mt < 4; mt++) {
                uint32_t roff = (uint32_t)((wm * 64 + mt * 16) * (TP * 2) + ks * 32);
                ldsm4(ah[mt], aAh + roff + a_lane);
                ldsm4(al[mt], aAl + roff + a_lane);
            }
#pragma unroll
            for (int nt = 0; nt < 4; nt++) {
                uint32_t bh[2], bl[2];
                uint32_t roff = (uint32_t)((wn * 32 + nt * 8) * (TP * 2) + ks * 32);
                ldsm2(bh, aBh + roff + b_lane);
                ldsm2(bl, aBl + roff + b_lane);
#pragma unroll
                for (int mt = 0; mt < 4; mt++) {
                    mma_bf16(acc[mt][nt], ah[mt], bh);
                    mma_bf16(acc[mt][nt], al[mt], bh);
                    mma_bf16(acc[mt][nt], ah[mt], bl);
                }
            }
        }
        __syncthreads();
    }

    const int tq = lid >> 2, tr = lid & 3;

    if (!pool) {
        // plain epilogue: bias (+relu) and store fp32 rows
#pragma unroll
        for (int mt = 0; mt < 4; mt++) {
#pragma unroll
            for (int h = 0; h < 2; h++) {
                int node = node0 + wm * 64 + mt * 16 + tq + h * 8;
                if (node >= NN) continue;
#pragma unroll
                for (int nt = 0; nt < 4; nt++) {
                    int col = wn * 32 + nt * 8 + tr * 2;
                    float v0 = acc[mt][nt][h * 2 + 0] + sbias[col];
                    float v1 = acc[mt][nt][h * 2 + 1] + sbias[col + 1];
                    if (relu) { v0 = fmaxf(v0, 0.f); v1 = fmaxf(v1, 0.f); }
                    *(float2*)(OUT + (size_t)node * FD + col) = make_float2(v0, v1);
                }
            }
        }
        return;
    }

    // fused pooling epilogue (layer 1): segment sum/max per graph, no OUT write
    float* psumS = (float*)smem;                      // [POOL_SEGS][128]
    float* pmaxS = (float*)smem + POOL_SEGS * 128;    // [POOL_SEGS][128]
    for (int i = tid; i < POOL_SEGS * 128; i += 256) {
        psumS[i] = 0.f;
        pmaxS[i] = -INFINITY;
    }
    __syncthreads();

    int seg0 = sbatch[0];
    int lastn = min(127, NN - 1 - node0);
    int span = sbatch[lastn] - seg0;                  // inclusive span - 1
    bool fast = (span < POOL_SEGS);

    int curseg = -1;
    float aS[8], aM[8];
#pragma unroll
    for (int j = 0; j < 8; j++) { aS[j] = 0.f; aM[j] = -INFINITY; }

    for (int mt = 0; mt < 4; mt++) {
        for (int h = 0; h < 2; h++) {
            int ln = wm * 64 + mt * 16 + tq + h * 8;
            int node = node0 + ln;
            if (node >= NN) continue;
            int seg = sbatch[ln];
            if (seg != curseg) {
                if (curseg >= 0) {
#pragma unroll
                    for (int j = 0; j < 8; j++) {
                        int col = wn * 32 + (j >> 1) * 8 + tr * 2 + (j & 1);
                        if (fast) {
                            atomicAdd(&psumS[(curseg - seg0) * 128 + col], aS[j]);
                            atomicMaxF(&pmaxS[(curseg - seg0) * 128 + col], aM[j]);
                        } else {
                            atomicAdd(&g_psum[curseg * 128 + col], aS[j]);
                            atomicMaxF(&g_pmax[curseg * 128 + col], aM[j]);
                        }
                        aS[j] = 0.f; aM[j] = -INFINITY;
                    }
                }
                curseg = seg;
            }
#pragma unroll
            for (int nt = 0; nt < 4; nt++) {
#pragma unroll
                for (int cc = 0; cc < 2; cc++) {
                    int col = wn * 32 + nt * 8 + tr * 2 + cc;
                    float v = acc[mt][nt][h * 2 + cc] + sbias[col];
                    int j = nt * 2 + cc;
                    aS[j] += v;
                    aM[j] = fmaxf(aM[j], v);
                }
            }
        }
    }
    if (curseg >= 0) {
#pragma unroll
        for (int j = 0; j < 8; j++) {
            int col = wn * 32 + (j >> 1) * 8 + tr * 2 + (j & 1);
            if (fast) {
                atomicAdd(&psumS[(curseg - seg0) * 128 + col], aS[j]);
                atomicMaxF(&pmaxS[(curseg - seg0) * 128 + col], aM[j]);
            } else {
                atomicAdd(&g_psum[curseg * 128 + col], aS[j]);
                atomicMaxF(&g_pmax[curseg * 128 + col], aM[j]);
            }
        }
    }
    __syncthreads();
    if (fast) {
        for (int i = tid; i < (span + 1) * 128; i += 256) {
            int s = i >> 7, col = i & 127;
            atomicAdd(&g_psum[(seg0 + s) * 128 + col], psumS[s * 128 + col]);
            atomicMaxF(&g_pmax[(seg0 + s) * 128 + col], pmaxS[s * 128 + col]);
        }
    }
}

// ---------------- readout head ---------------------------------------------
__global__ void k_readout(const float* __restrict__ gfeat,
                          const float* __restrict__ Wg, const float* __restrict__ bg,
                          const float* __restrict__ Wo, const float* __restrict__ bo,
                          float* __restrict__ out) {
    __shared__ float flat[3 * FD];
    __shared__ float logits[2];
    int g = blockIdx.x, o = threadIdx.x;     // 128 threads
    float cnt = fmaxf((float)g_pcnt[g], 1.f);
    flat[o]       = g_psum[g * FD + o] / cnt;
    flat[FD + o]  = g_pmax[g * FD + o];
    float acc = bg[o];
#pragma unroll
    for (int k = 0; k < GF; k++) acc += gfeat[g * GF + k] * Wg[k * FD + o];
    flat[2 * FD + o] = acc;
    __syncthreads();
    if (o < 2) {
        float l = bo[o];
        for (int j = 0; j < 3 * FD; j++) l += flat[j] * Wo[j * 2 + o];
        logits[o] = l;
    }
    __syncthreads();
    if (o < 2) {
        float mm  = fmaxf(logits[0], logits[1]);
        float lse = mm + logf(expf(logits[0] - mm) + expf(logits[1] - mm));
        out[g * 2 + o] = logits[o] - lse;
    }
}

// ---------------- launch -----------------------------------------------------
extern "C" void kernel_launch(void* const* d_in, const int* in_sizes, int n_in,
                              void* d_out, int out_size) {
    const float* x     = (const float*)d_in[0];
    const int*   edges = (const int*)  d_in[1];
    const int*   batch = (const int*)  d_in[2];
    const float* gfeat = (const float*)d_in[3];
    const float* Wl0   = (const float*)d_in[4];
    const float* bl0   = (const float*)d_in[5];
    const float* Wr0   = (const float*)d_in[6];
    const float* Wl1   = (const float*)d_in[7];
    const float* bl1   = (const float*)d_in[8];
    const float* Wr1   = (const float*)d_in[9];
    const float* Wg    = (const float*)d_in[10];
    const float* bg    = (const float*)d_in[11];
    const float* Wo    = (const float*)d_in[12];
    const float* bo    = (const float*)d_in[13];
    float* out = (float*)d_out;

    cudaFuncSetAttribute(k_gemm, cudaFuncAttributeMaxDynamicSharedMemorySize,
                         GEMM_SMEM);

    __nv_bfloat16 *pBh, *pBl;
    float *p_agg, *p_h0;
    cudaGetSymbolAddress((void**)&pBh, g_Bh);
    cudaGetSymbolAddress((void**)&pBl, g_Bl);
    cudaGetSymbolAddress((void**)&p_agg, g_aggf);
    cudaGetSymbolAddress((void**)&p_h0, g_h0);

    const int scan_nb = (NN + SCAN_B - 1) / SCAN_B;   // 98
    const int gemm_nb = (NN + 127) / 128;             // 782

    k_init<<<(NN + 255) / 256, 256>>>();
    k_hist<<<(NE + 255) / 256, 256>>>(edges);
    k_scanA<<<scan_nb, SCAN_B>>>();
    k_scanB<<<1, 128>>>(scan_nb);
    k_scanC<<<scan_nb, SCAN_B>>>();
    k_fillcol<<<(NE + 255) / 256, 256>>>(edges);

    k_prepw<<<256, 256>>>(Wr0, Wl0, Wr1, Wl1);
    k_cnt<<<1, 128>>>(batch);

    // layer 0
    k_aggregate<<<(NN + 7) / 8, 256>>>(x);
    k_gemm<<<gemm_nb, 256, GEMM_SMEM>>>(x, p_agg, pBh, pBl, bl0, p_h0,
                                        nullptr, 1, 0);
    // layer 1 (pooling fused into epilogue)
    k_aggregate<<<(NN + 7) / 8, 256>>>(p_h0);
    k_gemm<<<gemm_nb, 256, GEMM_SMEM>>>(p_h0, p_agg, pBh + 32768, pBl + 32768,
                                        bl1, nullptr, batch, 0, 1);

    k_readout<<<NG, FD>>>(gfeat, Wg, bg, Wo, bo, out);
}